// round 4
// baseline (speedup 1.0000x reference)
#include <cuda_runtime.h>

// out[row, t] = x[row, t - s]  if 0 <= t - s < T else 0
// rows = 256, T = 160000 (T % 4 == 0), s = shifts[row] - max_shift in [-16000, 16000]
//
// Block tile = WPB float4-words of one row; each thread owns VEC=8 words strided
// by blockDim. All loads front-batched (MLP=8 words/thread) before any store.
// Loads use default eviction (x gets partial cross-iteration L2 residency);
// stores use __stcs evict-first (output has zero reuse, don't evict x).
// Interior tiles (~90%) skip all bounds predication.

#define VEC 8
#define THREADS 256
#define WPB (VEC * THREADS)   // 2048 float4 words = 8192 floats per tile

__global__ void __launch_bounds__(THREADS)
random_shift_kernel(const float* __restrict__ x,
                    const int* __restrict__ shifts,
                    float4* __restrict__ out4,
                    int T, int max_shift) {
    const int row = blockIdx.y;
    const int s = shifts[row] - max_shift;

    const int T4 = T >> 2;
    const int tile0 = blockIdx.x * WPB;                    // first word of tile
    const size_t ebase = (size_t)row * (size_t)T;          // element base
    const size_t wbase = (size_t)row * (size_t)T4;         // word base
    const float* __restrict__ xr = x + ebase;

    // tile source element range: [4*tile0 - s, 4*(tile0+WPB) - s)
    const int src_lo = 4 * tile0 - s;
    const int src_hi = 4 * (tile0 + WPB) - s;
    const bool interior = (src_lo >= 0) && (src_hi <= T) && (tile0 + WPB <= T4);

    float4 v[VEC];

    if (interior) {
#pragma unroll
        for (int k = 0; k < VEC; ++k) {
            const int u = 4 * (tile0 + (int)threadIdx.x + k * THREADS) - s;
            v[k].x = __ldg(xr + u);
            v[k].y = __ldg(xr + u + 1);
            v[k].z = __ldg(xr + u + 2);
            v[k].w = __ldg(xr + u + 3);
        }
#pragma unroll
        for (int k = 0; k < VEC; ++k) {
            const int w = tile0 + threadIdx.x + k * THREADS;
            __stcs(out4 + wbase + w, v[k]);
        }
    } else {
#pragma unroll
        for (int k = 0; k < VEC; ++k) {
            const int w = tile0 + threadIdx.x + k * THREADS;
            const int u = 4 * w - s;
            float t0 = 0.f, t1 = 0.f, t2 = 0.f, t3 = 0.f;
            if (w < T4) {
                if (u >= 0 && u + 3 < T) {
                    t0 = __ldg(xr + u);
                    t1 = __ldg(xr + u + 1);
                    t2 = __ldg(xr + u + 2);
                    t3 = __ldg(xr + u + 3);
                } else {
                    if (u >= 0     && u < T)     t0 = __ldg(xr + u);
                    if (u + 1 >= 0 && u + 1 < T) t1 = __ldg(xr + u + 1);
                    if (u + 2 >= 0 && u + 2 < T) t2 = __ldg(xr + u + 2);
                    if (u + 3 >= 0 && u + 3 < T) t3 = __ldg(xr + u + 3);
                }
            }
            v[k] = make_float4(t0, t1, t2, t3);
        }
#pragma unroll
        for (int k = 0; k < VEC; ++k) {
            const int w = tile0 + threadIdx.x + k * THREADS;
            if (w < T4)
                __stcs(out4 + wbase + w, v[k]);
        }
    }
}

extern "C" void kernel_launch(void* const* d_in, const int* in_sizes, int n_in,
                              void* d_out, int out_size) {
    const float* x      = (const float*)d_in[0];
    const int*   shifts = (const int*)d_in[1];
    float4*      out4   = (float4*)d_out;

    const int rows = in_sizes[1];            // B*M = 256
    const int T    = in_sizes[0] / rows;     // 160000
    const int T4   = T / 4;                  // 40000
    const int max_shift = T / 10;            // 16000

    dim3 grid((T4 + WPB - 1) / WPB, rows);   // (20, 256)
    random_shift_kernel<<<grid, THREADS>>>(x, shifts, out4, T, max_shift);
}

// round 6
// speedup vs baseline: 1.0198x; 1.0198x over previous
#include <cuda_runtime.h>

// out[row, t] = x[row, t - s]  if 0 <= t - s < T else 0
// rows = 256, T = 160000 (T % 8 == 0), s = shifts[row] - max_shift in [-16000, 16000]
//
// Interior path: aligned 256-bit loads (ld.global.v4.b64). Rows < resident_rows
// use L2::evict_last so a ~96MB slice of x stays L2-resident across graph
// replays. Misalignment a = (-s) mod 8 is row-uniform; each thread loads the
// two covering aligned octets and recombines via a uniform switch. Stores are
// evict-first (__stcs). Edge tiles: scalar predicated path.

#define OPT 2                 // octets (8 floats) per thread
#define THREADS 256
#define OCTPB (OPT * THREADS) // 512 octets = 4096 floats per tile

__device__ __forceinline__ void ld256(const float* p, float f[8], bool evict_last) {
    unsigned long long a0, a1, a2, a3;
    if (evict_last) {
        asm volatile("ld.global.L2::evict_last.v4.b64 {%0,%1,%2,%3}, [%4];"
                     : "=l"(a0), "=l"(a1), "=l"(a2), "=l"(a3) : "l"(p));
    } else {
        asm volatile("ld.global.v4.b64 {%0,%1,%2,%3}, [%4];"
                     : "=l"(a0), "=l"(a1), "=l"(a2), "=l"(a3) : "l"(p));
    }
    f[0] = __uint_as_float((unsigned)a0); f[1] = __uint_as_float((unsigned)(a0 >> 32));
    f[2] = __uint_as_float((unsigned)a1); f[3] = __uint_as_float((unsigned)(a1 >> 32));
    f[4] = __uint_as_float((unsigned)a2); f[5] = __uint_as_float((unsigned)(a2 >> 32));
    f[6] = __uint_as_float((unsigned)a3); f[7] = __uint_as_float((unsigned)(a3 >> 32));
}

// out octet = elements [a, a+8) of the 16-float window L||H  (a uniform per row)
__device__ __forceinline__ void sel_shift(const float L[8], const float H[8], int a,
                                          float4& v0, float4& v1) {
    switch (a) {
    case 0: v0 = make_float4(L[0],L[1],L[2],L[3]); v1 = make_float4(L[4],L[5],L[6],L[7]); break;
    case 1: v0 = make_float4(L[1],L[2],L[3],L[4]); v1 = make_float4(L[5],L[6],L[7],H[0]); break;
    case 2: v0 = make_float4(L[2],L[3],L[4],L[5]); v1 = make_float4(L[6],L[7],H[0],H[1]); break;
    case 3: v0 = make_float4(L[3],L[4],L[5],L[6]); v1 = make_float4(L[7],H[0],H[1],H[2]); break;
    case 4: v0 = make_float4(L[4],L[5],L[6],L[7]); v1 = make_float4(H[0],H[1],H[2],H[3]); break;
    case 5: v0 = make_float4(L[5],L[6],L[7],H[0]); v1 = make_float4(H[1],H[2],H[3],H[4]); break;
    case 6: v0 = make_float4(L[6],L[7],H[0],H[1]); v1 = make_float4(H[2],H[3],H[4],H[5]); break;
    default:v0 = make_float4(L[7],H[0],H[1],H[2]); v1 = make_float4(H[3],H[4],H[5],H[6]); break;
    }
}

__global__ void __launch_bounds__(THREADS)
random_shift_kernel(const float* __restrict__ x,
                    const int* __restrict__ shifts,
                    float4* __restrict__ out4,
                    int T, int max_shift, int resident_rows) {
    const int row = blockIdx.y;
    const int s = shifts[row] - max_shift;
    const bool resident = row < resident_rows;

    const int TOCT = T >> 3;                 // octets per row
    const int oct0 = blockIdx.x * OCTPB;
    const size_t ebase = (size_t)row * (size_t)T;
    const float* __restrict__ xr = x + ebase;

    const int src_lo = 8 * oct0 - s;
    const int src_hi = 8 * (oct0 + OCTPB) - s;
    const bool interior = (src_lo >= 0) && (src_hi + 8 <= T) && (oct0 + OCTPB <= TOCT);

    if (interior) {
        const int a = (int)(((unsigned)(-s)) & 7u);   // row-uniform intra-octet offset
        float L[OPT][8], H[OPT][8];
#pragma unroll
        for (int k = 0; k < OPT; ++k) {
            const int oct = oct0 + (int)threadIdx.x + k * THREADS;
            const int u0  = 8 * oct - s;
            const int q   = (u0 - a) >> 3;            // aligned source octet
            ld256(xr + 8 * q,     L[k], resident);
            ld256(xr + 8 * q + 8, H[k], resident);
        }
#pragma unroll
        for (int k = 0; k < OPT; ++k) {
            const int oct = oct0 + (int)threadIdx.x + k * THREADS;
            float4 v0, v1;
            sel_shift(L[k], H[k], a, v0, v1);
            __stcs(out4 + (ebase >> 2) + 2 * (size_t)oct,     v0);
            __stcs(out4 + (ebase >> 2) + 2 * (size_t)oct + 1, v1);
        }
    } else {
#pragma unroll
        for (int k = 0; k < OPT; ++k) {
            const int oct = oct0 + (int)threadIdx.x + k * THREADS;
            if (oct >= TOCT) continue;
            const int u0 = 8 * oct - s;
            float f[8];
#pragma unroll
            for (int e = 0; e < 8; ++e) {
                const int u = u0 + e;
                f[e] = (u >= 0 && u < T) ? __ldg(xr + u) : 0.0f;
            }
            __stcs(out4 + (ebase >> 2) + 2 * (size_t)oct,
                   make_float4(f[0], f[1], f[2], f[3]));
            __stcs(out4 + (ebase >> 2) + 2 * (size_t)oct + 1,
                   make_float4(f[4], f[5], f[6], f[7]));
        }
    }
}

extern "C" void kernel_launch(void* const* d_in, const int* in_sizes, int n_in,
                              void* d_out, int out_size) {
    const float* x      = (const float*)d_in[0];
    const int*   shifts = (const int*)d_in[1];
    float4*      out4   = (float4*)d_out;

    const int rows = in_sizes[1];            // B*M = 256
    const int T    = in_sizes[0] / rows;     // 160000
    const int TOCT = T / 8;                  // 20000
    const int max_shift = T / 10;            // 16000

    // Keep ~96 MB of x L2-resident: bytes/row = T*4 = 640 KB -> 150 rows.
    const long long row_bytes = (long long)T * 4;
    int resident_rows = (int)(96LL * 1024 * 1024 / row_bytes);
    if (resident_rows > rows) resident_rows = rows;

    dim3 grid((TOCT + OCTPB - 1) / OCTPB, rows);   // (40, 256)
    random_shift_kernel<<<grid, THREADS>>>(x, shifts, out4, T, max_shift,
                                           resident_rows);
}